// round 4
// baseline (speedup 1.0000x reference)
#include <cuda_runtime.h>
#include <cstdint>

#define GQ     640
#define NIMG   320
#define NCOIL  12
#define MPTS   102400
#define PI_F   3.14159265358979f
#define BETA_F 13.855101f      // pi * sqrt((6*1.5/2)^2 - 0.8)
#define INV_G  0.0015625f      // 1/640

// Scratch (zero-initialized at module load; middle rows of g_gridA are never
// written by anyone, so they remain zero across graph replays).
__device__ float2 g_gridA[NCOIL * GQ * GQ];                 // [coil][row][col]
__device__ __align__(16) float2 g_gridC[GQ * GQ * NCOIL];   // [row][col][coil]
__device__ float  g_scale[NIMG];
__device__ float2 g_tw[GQ];                                 // exp(-2*pi*i*k/640)

__constant__ float c5r[5] = {1.0f, 0.30901699f, -0.80901699f, -0.80901699f, 0.30901699f};
__constant__ float c5i[5] = {0.0f, -0.95105652f, -0.58778525f, 0.58778525f, 0.95105652f};

// ---------------------------------------------------------------------------
// Modified Bessel I0 (Abramowitz & Stegun, ~2e-7 rel error)
// ---------------------------------------------------------------------------
__device__ __forceinline__ float i0f_dev(float x) {
    if (x < 3.75f) {
        float t = x * (1.0f / 3.75f);
        t *= t;
        return 1.0f + t * (3.5156229f + t * (3.0899424f + t * (1.2067492f
             + t * (0.2659732f + t * (0.0360768f + t * 0.0045813f)))));
    } else {
        float t = 3.75f / x;
        float p = 0.39894228f + t * (0.01328592f + t * (0.00225319f + t * (-0.00157565f
                + t * (0.00916281f + t * (-0.02057706f + t * (0.02635537f
                + t * (-0.01647633f + t * 0.00392377f)))))));
        return expf(x) * rsqrtf(x) * p;
    }
}

// Kaiser-Bessel kernel, support |u| <= 3 (J=6)
__device__ __forceinline__ float kbf(float u) {
    float m = fabsf(u) * (1.0f / 3.0f);
    float a = 1.0f - m * m;
    a = a > 0.0f ? a : 0.0f;
    float v = i0f_dev(BETA_F * sqrtf(a)) * (1.0f / 6.0f);
    return (m <= 1.0f) ? v : 0.0f;
}

// ---------------------------------------------------------------------------
// Apodization scale (length 320) + twiddle table (length 640). block = 640.
// ---------------------------------------------------------------------------
__global__ void apod_kernel() {
    int n = threadIdx.x;
    if (n < NIMG) {
        float acc = 0.0f;
        #pragma unroll
        for (int j = -6; j <= 6; j++) {
            float kv = kbf((float)j);
            acc += kv * cosf(2.0f * PI_F * (float)j * ((float)n - 160.0f) * (1.0f / 640.0f));
        }
        g_scale[n] = 1.0f / acc;
    }
    if (n < GQ) {
        float sn, cs;
        sincospif(-(float)n * (1.0f / 320.0f), &sn, &cs);   // -2*pi*n/640
        g_tw[n] = make_float2(cs, sn);
    }
}

// ---------------------------------------------------------------------------
// 640-point forward FFT in shared memory. 640 = 5 * 128.
// Twiddles from smem LUT tw[k] = exp(-2 pi i k / 640).
// Input layout in A:  A[n1*128 + n2] = x[5*n2 + n1]
// Output (natural order X[k]) ends in A. Requires blockDim.x == 320.
// ---------------------------------------------------------------------------
__device__ void fft640(float2* A, float2* B, const float2* tw, int t) {
    float2* src = A;
    float2* dst = B;
    const int n1 = t >> 6;
    const int b  = t & 63;
    #pragma unroll
    for (int stage = 0; stage < 7; stage++) {
        int s = 1 << stage;
        int m = 64 >> stage;
        int q = b & (s - 1);
        int p = b >> stage;
        float2 a  = src[(n1 << 7) + q + s * p];
        float2 bb = src[(n1 << 7) + q + s * (p + m)];
        float2 wv = tw[p * (5 << stage)];        // exp(-2 pi i p / (128>>stage))
        float2 e = make_float2(a.x + bb.x, a.y + bb.y);
        float dx = a.x - bb.x, dy = a.y - bb.y;
        float2 o = make_float2(dx * wv.x - dy * wv.y, dx * wv.y + dy * wv.x);
        dst[(n1 << 7) + q + s * 2 * p]       = e;
        dst[(n1 << 7) + q + s * (2 * p + 1)] = o;
        __syncthreads();
        float2* tmp = src; src = dst; dst = tmp;
    }
    if (t < 128) {
        int k2 = t;
        float2 g[5];
        #pragma unroll
        for (int j = 0; j < 5; j++) {
            float2 f = src[(j << 7) + k2];
            float2 wv = tw[j * k2];              // j*k2 <= 508 < 640
            g[j] = make_float2(f.x * wv.x - f.y * wv.y, f.x * wv.y + f.y * wv.x);
        }
        #pragma unroll
        for (int k1 = 0; k1 < 5; k1++) {
            float rx = 0.0f, ry = 0.0f;
            #pragma unroll
            for (int j = 0; j < 5; j++) {
                int id = (j * k1) % 5;
                float cr = c5r[id], ci = c5i[id];
                rx += g[j].x * cr - g[j].y * ci;
                ry += g[j].x * ci + g[j].y * cr;
            }
            dst[(k1 << 7) + k2] = make_float2(rx, ry);
        }
    }
    __syncthreads();
}

// ---------------------------------------------------------------------------
// Row pass: fused coil-multiply + apodization + pad + ifftshift + row FFT.
// ---------------------------------------------------------------------------
__global__ void row_fft_kernel(const float* __restrict__ img_r, const float* __restrict__ img_i,
                               const float* __restrict__ sm_r,  const float* __restrict__ sm_i) {
    __shared__ float2 A[GQ];
    __shared__ float2 B[GQ];
    __shared__ float2 tw[GQ];
    int coil = blockIdx.y;
    int rr   = blockIdx.x;
    int r = (rr < 160) ? rr : rr + 320;
    int i = (rr < 160) ? rr + 160 : rr - 160;
    int t = threadIdx.x;
    float si = g_scale[i];

    #pragma unroll
    for (int kk = 0; kk < 2; kk++) {
        int cc = t + kk * 320;
        tw[cc] = g_tw[cc];
        float2 v = make_float2(0.0f, 0.0f);
        if (cc < 160 || cc >= 480) {
            int j = (cc < 160) ? cc + 160 : cc - 480;
            float ir  = img_r[i * NIMG + j];
            float ii  = img_i[i * NIMG + j];
            float sr  = sm_r[((size_t)coil * NIMG + i) * NIMG + j];
            float sim = sm_i[((size_t)coil * NIMG + i) * NIMG + j];
            float sc  = si * g_scale[j];
            v.x = (ir * sr - ii * sim) * sc;
            v.y = (ir * sim + ii * sr) * sc;
        }
        A[(cc % 5) * 128 + cc / 5] = v;
    }
    __syncthreads();
    fft640(A, B, tw, t);
    float2* gout = g_gridA + ((size_t)coil * GQ + r) * GQ;
    for (int k = t; k < GQ; k += 320) gout[k] = A[k];
}

// ---------------------------------------------------------------------------
// Column pass: 4 columns per block staged through SMEM (only the 320 nonzero
// rows are loaded; middle rows zero-filled). Writes coil-INTERLEAVED grid:
// g_gridC[(row*GQ+col)*NCOIL + coil] (x 1/640).
// ---------------------------------------------------------------------------
#define COLS_PER_BLK 4
#define SPITCH 642
__global__ void col_fft_kernel() {
    __shared__ float2 S[COLS_PER_BLK * SPITCH];
    __shared__ float2 A[GQ];
    __shared__ float2 B[GQ];
    __shared__ float2 tw[GQ];
    int coil = blockIdx.y;
    int c0 = blockIdx.x * COLS_PER_BLK;
    const float2* gin = g_gridA + (size_t)coil * GQ * GQ;

    for (int k = threadIdx.x; k < GQ; k += 320) tw[k] = g_tw[k];

    // load 320 nonzero rows; zero the middle 320
    for (int idx = threadIdx.x; idx < 320 * COLS_PER_BLK; idx += 320) {
        int rr = idx >> 2, col = idx & 3;
        int row = (rr < 160) ? rr : rr + 320;
        S[col * SPITCH + row]      = gin[(size_t)row * GQ + c0 + col];
        S[col * SPITCH + 160 + rr] = make_float2(0.0f, 0.0f);
    }
    __syncthreads();

    for (int col = 0; col < COLS_PER_BLK; col++) {
        for (int k = threadIdx.x; k < GQ; k += 320)
            A[(k % 5) * 128 + k / 5] = S[col * SPITCH + k];
        __syncthreads();
        fft640(A, B, tw, threadIdx.x);
        for (int k = threadIdx.x; k < GQ; k += 320) {
            float2 v = A[k];
            g_gridC[((size_t)k * GQ + c0 + col) * NCOIL + coil] =
                make_float2(v.x * INV_G, v.y * INV_G);
        }
        __syncthreads();
    }
}

// ---------------------------------------------------------------------------
// Interpolation v4: warp-per-sample on coil-interleaved grid, float4 gathers.
// 72 (j,coil) slots per sample; lane P handles the slot pair (2P, 2P+1)
// (same y-tap j, adjacent coils -> one aligned float4); lanes 0..3 take the
// remaining 4 pairs of the j=5 group. 36 LDG.128 per row-iter per warp.
// ---------------------------------------------------------------------------
#define WPB 8   // warps (samples) per block
__global__ void __launch_bounds__(32 * WPB) interp_kernel(const float* __restrict__ ktraj,
                                                          float* __restrict__ out) {
    __shared__ __align__(16) float2 s_part[WPB][72];
    __shared__ float2 s_out[NCOIL][WPB];
    const int warp = threadIdx.x >> 5;
    const int lane = threadIdx.x & 31;
    const int m = blockIdx.x * WPB + warp;

    // --- taps in lanes 0..11: lane = dim*6 + j ---
    float w = 0.0f;
    int   ki = 0;
    if (lane < 12) {
        int dim = lane >= 6 ? 1 : 0;
        int j   = lane - dim * 6;
        float om = ktraj[dim * MPTS + m];
        float tt = fmodf((om * 640.0f) / 6.2831855f, 640.0f);
        if (tt < 0.0f) tt += 640.0f;
        float base = floorf(tt);
        float k = base + (float)(j - 2);
        w = kbf(tt - k);
        ki = (int)k;
        if (ki < 0) ki += 640;
        else if (ki >= 640) ki -= 640;
    }

    const unsigned FULL = 0xFFFFFFFFu;
    // pair A: slots (2*lane, 2*lane+1): j = lane/6, c = 2*lane - 12*j (even)
    const int jA = lane / 6;
    const int cA = 2 * lane - 12 * jA;
    float wyA = __shfl_sync(FULL, w, 6 + jA);
    int   iyA = __shfl_sync(FULL, ki, 6 + jA);
    const int offA = iyA * NCOIL + cA;
    // pair B (lanes 0..3): slots 64+2l, 65+2l: j = 5, c = 4 + 2*lane
    const bool hasB = (lane < 4);
    float wyB = __shfl_sync(FULL, w, 11);
    int   iyB = __shfl_sync(FULL, ki, 11);
    const int offB = iyB * NCOIL + 4 + 2 * lane;

    float4 accA = make_float4(0.f, 0.f, 0.f, 0.f);
    float4 accB = make_float4(0.f, 0.f, 0.f, 0.f);

    #pragma unroll
    for (int i = 0; i < 6; i++) {
        float wx = __shfl_sync(FULL, w, i);
        int   ix = __shfl_sync(FULL, ki, i);
        const float2* __restrict__ rowp = g_gridC + (size_t)ix * (GQ * NCOIL);
        float4 vA = *(const float4*)(rowp + offA);
        accA.x += wx * vA.x; accA.y += wx * vA.y;
        accA.z += wx * vA.z; accA.w += wx * vA.w;
        if (hasB) {
            float4 vB = *(const float4*)(rowp + offB);
            accB.x += wx * vB.x; accB.y += wx * vB.y;
            accB.z += wx * vB.z; accB.w += wx * vB.w;
        }
    }

    *(float4*)&s_part[warp][2 * lane] =
        make_float4(wyA * accA.x, wyA * accA.y, wyA * accA.z, wyA * accA.w);
    if (hasB)
        *(float4*)&s_part[warp][64 + 2 * lane] =
            make_float4(wyB * accB.x, wyB * accB.y, wyB * accB.z, wyB * accB.w);
    __syncwarp();

    if (lane < 12) {
        float rx = 0.f, ry = 0.f;
        #pragma unroll
        for (int j = 0; j < 6; j++) {
            float2 p = s_part[warp][j * 12 + lane];
            rx += p.x; ry += p.y;
        }
        s_out[lane][warp] = make_float2(rx, ry);
    }
    __syncthreads();

    if (threadIdx.x < NCOIL * WPB) {
        int c = threadIdx.x >> 3;
        int s = threadIdx.x & 7;
        ((float2*)out)[(size_t)c * MPTS + blockIdx.x * WPB + s] = s_out[c][s];
    }
}

// ---------------------------------------------------------------------------
extern "C" void kernel_launch(void* const* d_in, const int* in_sizes, int n_in,
                              void* d_out, int out_size) {
    const float* img_r = (const float*)d_in[0];
    const float* img_i = (const float*)d_in[1];
    const float* sm_r  = (const float*)d_in[2];
    const float* sm_i  = (const float*)d_in[3];
    const float* kt    = (const float*)d_in[4];
    float* out = (float*)d_out;

    apod_kernel<<<1, 640>>>();
    row_fft_kernel<<<dim3(320, NCOIL), 320>>>(img_r, img_i, sm_r, sm_i);
    col_fft_kernel<<<dim3(GQ / COLS_PER_BLK, NCOIL), 320>>>();
    interp_kernel<<<MPTS / WPB, 32 * WPB>>>(kt, out);
}

// round 5
// speedup vs baseline: 1.0993x; 1.0993x over previous
#include <cuda_runtime.h>
#include <cstdint>

#define GQ     640
#define NIMG   320
#define NCOIL  12
#define MPTS   102400
#define PI_F   3.14159265358979f
#define BETA_F 13.855101f      // pi * sqrt((6*1.5/2)^2 - 0.8)
#define INV_G  0.0015625f      // 1/640

// Scratch (zero-initialized at module load).
__device__ float2 g_gridA[NCOIL * GQ * GQ];                 // [coil][row][col]
__device__ float2 g_gridC[GQ * GQ * NCOIL];                 // [row][col][coil]
__device__ float  g_scale[NIMG];
__device__ float2 g_tw[GQ];                                 // exp(-2*pi*i*k/640)

__constant__ float c5r[5] = {1.0f, 0.30901699f, -0.80901699f, -0.80901699f, 0.30901699f};
__constant__ float c5i[5] = {0.0f, -0.95105652f, -0.58778525f, 0.58778525f, 0.95105652f};

// ---------------------------------------------------------------------------
// Modified Bessel I0 (Abramowitz & Stegun, ~2e-7 rel error)
// ---------------------------------------------------------------------------
__device__ __forceinline__ float i0f_dev(float x) {
    if (x < 3.75f) {
        float t = x * (1.0f / 3.75f);
        t *= t;
        return 1.0f + t * (3.5156229f + t * (3.0899424f + t * (1.2067492f
             + t * (0.2659732f + t * (0.0360768f + t * 0.0045813f)))));
    } else {
        float t = 3.75f / x;
        float p = 0.39894228f + t * (0.01328592f + t * (0.00225319f + t * (-0.00157565f
                + t * (0.00916281f + t * (-0.02057706f + t * (0.02635537f
                + t * (-0.01647633f + t * 0.00392377f)))))));
        return expf(x) * rsqrtf(x) * p;
    }
}

// Kaiser-Bessel kernel, support |u| <= 3 (J=6)
__device__ __forceinline__ float kbf(float u) {
    float m = fabsf(u) * (1.0f / 3.0f);
    float a = 1.0f - m * m;
    a = a > 0.0f ? a : 0.0f;
    float v = i0f_dev(BETA_F * sqrtf(a)) * (1.0f / 6.0f);
    return (m <= 1.0f) ? v : 0.0f;
}

// ---------------------------------------------------------------------------
// Apodization scale (length 320) + twiddle table (length 640). block = 640.
// ---------------------------------------------------------------------------
__global__ void apod_kernel() {
    int n = threadIdx.x;
    if (n < NIMG) {
        float acc = 0.0f;
        #pragma unroll
        for (int j = -6; j <= 6; j++) {
            float kv = kbf((float)j);
            acc += kv * cosf(2.0f * PI_F * (float)j * ((float)n - 160.0f) * (1.0f / 640.0f));
        }
        g_scale[n] = 1.0f / acc;
    }
    if (n < GQ) {
        float sn, cs;
        sincospif(-(float)n * (1.0f / 320.0f), &sn, &cs);   // -2*pi*n/640
        g_tw[n] = make_float2(cs, sn);
    }
}

__device__ __forceinline__ float2 cmul(float2 a, float2 b) {
    return make_float2(a.x * b.x - a.y * b.y, a.x * b.y + a.y * b.x);
}

// ---------------------------------------------------------------------------
// TWO 640-point forward FFTs per block phase. 640 = 5 * 128; 128 done as
// 3 composed radix-4 Stockham stages + 1 radix-2 stage (same values/order
// as 7 radix-2 stages), then twiddle + radix-5 combine.
// Abuf/Bbuf: [2][640]. Input in Abuf (layout A[f][ (cc%5)*128 + cc/5 ]),
// natural-order output ends in Bbuf. Requires blockDim.x == 320.
// Data flow: r4c0(A->B), r4c1(B->A), r4c2(A->B), r2(B->A), r5(A->B).
// ---------------------------------------------------------------------------
__device__ void fft640_pair(float2* Abuf, float2* Bbuf, const float2* tw, int t) {
    const int f  = (t >= 160) ? 1 : 0;        // warps 0-4 -> fft0, 5-9 -> fft1
    const int lt = t - 160 * f;               // 0..159
    const int n1 = lt >> 5;                   // sub-FFT 0..4
    const int u  = lt & 31;                   // butterfly index within sub-FFT
    float2* src = Abuf + f * 640;
    float2* dst = Bbuf + f * 640;

    #pragma unroll
    for (int c = 0; c < 3; c++) {
        const int sh = 2 * c;
        const int s  = 1 << sh;
        const int q  = u & (s - 1);
        const int pp = u >> sh;               // p' in [0, 32/s)
        const int br = (n1 << 7) + u;         // = n1*128 + q + s*p'
        float2 x0 = src[br];
        float2 x1 = src[br + 64];
        float2 x2 = src[br + 32];
        float2 x3 = src[br + 96];
        float2 w  = tw[(5 << sh) * pp];       // W_{2m}^{p'}
        float2 w2 = tw[(10 << sh) * pp];      // W_{m}^{p'}
        float2 A0 = make_float2(x0.x + x1.x, x0.y + x1.y);
        float2 d0 = make_float2(x0.x - x1.x, x0.y - x1.y);
        float2 A1 = cmul(d0, w);
        float2 B0 = make_float2(x2.x + x3.x, x2.y + x3.y);
        float2 d1 = make_float2(x2.x - x3.x, x2.y - x3.y);
        float2 t1 = cmul(d1, w);
        float2 B1 = make_float2(t1.y, -t1.x);            // -i * t1
        const int bw = (n1 << 7) + q + 4 * s * pp;
        float2 u2 = make_float2(A0.x - B0.x, A0.y - B0.y);
        float2 u3 = make_float2(A1.x - B1.x, A1.y - B1.y);
        dst[bw]         = make_float2(A0.x + B0.x, A0.y + B0.y);
        dst[bw + s]     = make_float2(A1.x + B1.x, A1.y + B1.y);
        dst[bw + 2 * s] = cmul(u2, w2);
        dst[bw + 3 * s] = cmul(u3, w2);
        __syncthreads();
        float2* tmp = src; src = dst; dst = tmp;
    }

    // final radix-2 stage (s=64, twiddle = 1): B -> A. Each thread does both ffts.
    {
        const int n1b = t / 64;               // t < 320 -> n1b 0..4
        const int qb  = t & 63;
        #pragma unroll
        for (int f2 = 0; f2 < 2; f2++) {
            float2* s2 = Bbuf + f2 * 640;     // after 3 composed stages data is in B
            float2* d2 = Abuf + f2 * 640;
            float2 a  = s2[(n1b << 7) + qb];
            float2 b2 = s2[(n1b << 7) + qb + 64];
            d2[(n1b << 7) + qb]      = make_float2(a.x + b2.x, a.y + b2.y);
            d2[(n1b << 7) + qb + 64] = make_float2(a.x - b2.x, a.y - b2.y);
        }
        __syncthreads();
    }

    // twiddle + radix-5 combine: A -> B (natural order). threads 0..255.
    if (t < 256) {
        const int f5 = t >> 7;
        const int k2 = t & 127;
        const float2* s5 = Abuf + f5 * 640;
        float2* d5 = Bbuf + f5 * 640;
        float2 g[5];
        #pragma unroll
        for (int j = 0; j < 5; j++) {
            float2 fv = s5[(j << 7) + k2];
            g[j] = cmul(fv, tw[j * k2]);      // j*k2 <= 508 < 640
        }
        #pragma unroll
        for (int k1 = 0; k1 < 5; k1++) {
            float rx = 0.0f, ry = 0.0f;
            #pragma unroll
            for (int j = 0; j < 5; j++) {
                int id = (j * k1) % 5;
                rx += g[j].x * c5r[id] - g[j].y * c5i[id];
                ry += g[j].x * c5i[id] + g[j].y * c5r[id];
            }
            d5[(k1 << 7) + k2] = make_float2(rx, ry);
        }
    }
    __syncthreads();
}

// ---------------------------------------------------------------------------
// Row pass: fused coil-multiply + apodization + pad + ifftshift + row FFT.
// 2 rows per block. grid = (160, 12), block = 320.
// ---------------------------------------------------------------------------
__global__ void __launch_bounds__(320) row_fft_kernel(
        const float* __restrict__ img_r, const float* __restrict__ img_i,
        const float* __restrict__ sm_r,  const float* __restrict__ sm_i) {
    __shared__ float2 A[2 * GQ];
    __shared__ float2 B[2 * GQ];
    __shared__ float2 tw[GQ];
    const int coil = blockIdx.y;
    const int pair = blockIdx.x;
    const int t = threadIdx.x;

    for (int k = t; k < GQ; k += 320) tw[k] = g_tw[k];

    #pragma unroll
    for (int f = 0; f < 2; f++) {
        int rr = pair * 2 + f;                         // 0..319
        int i  = (rr < 160) ? rr + 160 : rr - 160;     // source image row
        float si = g_scale[i];
        #pragma unroll
        for (int kk = 0; kk < 2; kk++) {
            int cc = t + kk * 320;
            float2 v = make_float2(0.0f, 0.0f);
            if (cc < 160 || cc >= 480) {
                int j = (cc < 160) ? cc + 160 : cc - 480;
                float ir  = img_r[i * NIMG + j];
                float ii  = img_i[i * NIMG + j];
                float sr  = sm_r[((size_t)coil * NIMG + i) * NIMG + j];
                float sim = sm_i[((size_t)coil * NIMG + i) * NIMG + j];
                float sc  = si * g_scale[j];
                v.x = (ir * sr - ii * sim) * sc;
                v.y = (ir * sim + ii * sr) * sc;
            }
            A[f * GQ + (cc % 5) * 128 + cc / 5] = v;
        }
    }
    __syncthreads();
    fft640_pair(A, B, tw, t);
    #pragma unroll
    for (int f = 0; f < 2; f++) {
        int rr = pair * 2 + f;
        int r  = (rr < 160) ? rr : rr + 320;           // shifted grid row
        float2* gout = g_gridA + ((size_t)coil * GQ + r) * GQ;
        for (int k = t; k < GQ; k += 320) gout[k] = B[f * GQ + k];
    }
}

// ---------------------------------------------------------------------------
// Column pass: 4 columns per block staged through SMEM (only the 320 nonzero
// rows loaded; middle zero-filled). FFTs done in 2 pair-phases. Writes the
// coil-INTERLEAVED grid g_gridC[(row*GQ+col)*NCOIL + coil] (x 1/640).
// ---------------------------------------------------------------------------
#define COLS_PER_BLK 4
#define SPITCH 642
__global__ void __launch_bounds__(320) col_fft_kernel() {
    __shared__ float2 S[COLS_PER_BLK * SPITCH];
    __shared__ float2 A[2 * GQ];
    __shared__ float2 B[2 * GQ];
    __shared__ float2 tw[GQ];
    const int coil = blockIdx.y;
    const int c0 = blockIdx.x * COLS_PER_BLK;
    const int t = threadIdx.x;
    const float2* gin = g_gridA + (size_t)coil * GQ * GQ;

    for (int k = t; k < GQ; k += 320) tw[k] = g_tw[k];

    for (int idx = t; idx < 320 * COLS_PER_BLK; idx += 320) {
        int rr = idx >> 2, col = idx & 3;
        int row = (rr < 160) ? rr : rr + 320;
        S[col * SPITCH + row]      = gin[(size_t)row * GQ + c0 + col];
        S[col * SPITCH + 160 + rr] = make_float2(0.0f, 0.0f);
    }
    __syncthreads();

    #pragma unroll
    for (int ph = 0; ph < 2; ph++) {
        #pragma unroll
        for (int f = 0; f < 2; f++) {
            int col = ph * 2 + f;
            for (int k = t; k < GQ; k += 320)
                A[f * GQ + (k % 5) * 128 + k / 5] = S[col * SPITCH + k];
        }
        __syncthreads();
        fft640_pair(A, B, tw, t);
        #pragma unroll
        for (int f = 0; f < 2; f++) {
            int col = ph * 2 + f;
            for (int k = t; k < GQ; k += 320) {
                float2 v = B[f * GQ + k];
                g_gridC[((size_t)k * GQ + c0 + col) * NCOIL + coil] =
                    make_float2(v.x * INV_G, v.y * INV_G);
            }
        }
        __syncthreads();
    }
}

// ---------------------------------------------------------------------------
// Interpolation (R2 version): ONE WARP PER SAMPLE on coil-interleaved grid.
// ---------------------------------------------------------------------------
#define WPB 8   // warps (samples) per block
__global__ void __launch_bounds__(32 * WPB) interp_kernel(const float* __restrict__ ktraj,
                                                          float* __restrict__ out) {
    __shared__ float2 s_part[WPB][72];
    __shared__ float2 s_out[NCOIL][WPB];
    const int warp = threadIdx.x >> 5;
    const int lane = threadIdx.x & 31;
    const int m = blockIdx.x * WPB + warp;

    float w = 0.0f;
    int   ki = 0;
    if (lane < 12) {
        int dim = lane >= 6 ? 1 : 0;
        int j   = lane - dim * 6;
        float om = ktraj[dim * MPTS + m];
        float tt = fmodf((om * 640.0f) / 6.2831855f, 640.0f);
        if (tt < 0.0f) tt += 640.0f;
        float base = floorf(tt);
        float k = base + (float)(j - 2);
        w = kbf(tt - k);
        ki = (int)k;
        if (ki < 0) ki += 640;
        else if (ki >= 640) ki -= 640;
    }

    const int e0 = lane, e1 = lane + 32, e2 = lane + 64;
    const int j0 = e0 / 12, j1 = e1 / 12;
    const int cc0 = e0 - j0 * 12, cc1 = e1 - j1 * 12, cc2 = e2 - 60;

    const unsigned FULL = 0xFFFFFFFFu;
    float wy0 = __shfl_sync(FULL, w, 6 + j0);
    float wy1 = __shfl_sync(FULL, w, 6 + j1);
    float wy2 = __shfl_sync(FULL, w, 11);
    int   iy0 = __shfl_sync(FULL, ki, 6 + j0);
    int   iy1 = __shfl_sync(FULL, ki, 6 + j1);
    int   iy2 = __shfl_sync(FULL, ki, 11);
    const int off0 = iy0 * NCOIL + cc0;
    const int off1 = iy1 * NCOIL + cc1;
    const int off2 = iy2 * NCOIL + cc2;
    const bool has2 = (lane < 8);

    float2 acc0 = make_float2(0.f, 0.f);
    float2 acc1 = make_float2(0.f, 0.f);
    float2 acc2 = make_float2(0.f, 0.f);

    #pragma unroll
    for (int i = 0; i < 6; i++) {
        float wx = __shfl_sync(FULL, w, i);
        int   ix = __shfl_sync(FULL, ki, i);
        const float2* __restrict__ rowp = g_gridC + (size_t)ix * (GQ * NCOIL);
        float2 v0 = __ldg(rowp + off0);
        float2 v1 = __ldg(rowp + off1);
        acc0.x += wx * v0.x; acc0.y += wx * v0.y;
        acc1.x += wx * v1.x; acc1.y += wx * v1.y;
        if (has2) {
            float2 v2 = __ldg(rowp + off2);
            acc2.x += wx * v2.x; acc2.y += wx * v2.y;
        }
    }

    s_part[warp][e0] = make_float2(wy0 * acc0.x, wy0 * acc0.y);
    s_part[warp][e1] = make_float2(wy1 * acc1.x, wy1 * acc1.y);
    if (has2) s_part[warp][e2] = make_float2(wy2 * acc2.x, wy2 * acc2.y);
    __syncwarp();

    if (lane < 12) {
        float rx = 0.f, ry = 0.f;
        #pragma unroll
        for (int j = 0; j < 6; j++) {
            float2 p = s_part[warp][j * 12 + lane];
            rx += p.x; ry += p.y;
        }
        s_out[lane][warp] = make_float2(rx, ry);
    }
    __syncthreads();

    if (threadIdx.x < NCOIL * WPB) {
        int c = threadIdx.x >> 3;
        int s = threadIdx.x & 7;
        ((float2*)out)[(size_t)c * MPTS + blockIdx.x * WPB + s] = s_out[c][s];
    }
}

// ---------------------------------------------------------------------------
extern "C" void kernel_launch(void* const* d_in, const int* in_sizes, int n_in,
                              void* d_out, int out_size) {
    const float* img_r = (const float*)d_in[0];
    const float* img_i = (const float*)d_in[1];
    const float* sm_r  = (const float*)d_in[2];
    const float* sm_i  = (const float*)d_in[3];
    const float* kt    = (const float*)d_in[4];
    float* out = (float*)d_out;

    apod_kernel<<<1, 640>>>();
    row_fft_kernel<<<dim3(160, NCOIL), 320>>>(img_r, img_i, sm_r, sm_i);
    col_fft_kernel<<<dim3(GQ / COLS_PER_BLK, NCOIL), 320>>>();
    interp_kernel<<<MPTS / WPB, 32 * WPB>>>(kt, out);
}

// round 6
// speedup vs baseline: 1.1541x; 1.0498x over previous
#include <cuda_runtime.h>
#include <cstdint>

#define GQ     640
#define NIMG   320
#define NCOIL  12
#define MPTS   102400
#define PI_F   3.14159265358979f
#define BETA_F 13.855101f      // pi * sqrt((6*1.5/2)^2 - 0.8)
#define INV_G  0.0015625f      // 1/640

// Bank swizzle for the FFT smem buffers (float2 elements):
// makes all Stockham radix-4 store patterns conflict-free.
#define SW(i) ((i) ^ (((i) >> 4) & 3))

// Scratch (zero-initialized at module load).
__device__ float2 g_gridA[NCOIL * GQ * GQ];                 // [coil][row][col]
__device__ float2 g_gridB[NCOIL * GQ * GQ];                 // [coil][row][col] after col FFT
__device__ float2 g_gridC[GQ * GQ * NCOIL];                 // [row][col][coil]
__device__ float  g_scale[NIMG];
__device__ float2 g_tw[GQ];                                 // exp(-2*pi*i*k/640)

__constant__ float c5r[5] = {1.0f, 0.30901699f, -0.80901699f, -0.80901699f, 0.30901699f};
__constant__ float c5i[5] = {0.0f, -0.95105652f, -0.58778525f, 0.58778525f, 0.95105652f};

// ---------------------------------------------------------------------------
// Modified Bessel I0 (Abramowitz & Stegun, ~2e-7 rel error)
// ---------------------------------------------------------------------------
__device__ __forceinline__ float i0f_dev(float x) {
    if (x < 3.75f) {
        float t = x * (1.0f / 3.75f);
        t *= t;
        return 1.0f + t * (3.5156229f + t * (3.0899424f + t * (1.2067492f
             + t * (0.2659732f + t * (0.0360768f + t * 0.0045813f)))));
    } else {
        float t = 3.75f / x;
        float p = 0.39894228f + t * (0.01328592f + t * (0.00225319f + t * (-0.00157565f
                + t * (0.00916281f + t * (-0.02057706f + t * (0.02635537f
                + t * (-0.01647633f + t * 0.00392377f)))))));
        return expf(x) * rsqrtf(x) * p;
    }
}

// Kaiser-Bessel kernel, support |u| <= 3 (J=6)
__device__ __forceinline__ float kbf(float u) {
    float m = fabsf(u) * (1.0f / 3.0f);
    float a = 1.0f - m * m;
    a = a > 0.0f ? a : 0.0f;
    float v = i0f_dev(BETA_F * sqrtf(a)) * (1.0f / 6.0f);
    return (m <= 1.0f) ? v : 0.0f;
}

// ---------------------------------------------------------------------------
// Apodization scale (length 320) + twiddle table (length 640). block = 640.
// ---------------------------------------------------------------------------
__global__ void apod_kernel() {
    int n = threadIdx.x;
    if (n < NIMG) {
        float acc = 0.0f;
        #pragma unroll
        for (int j = -6; j <= 6; j++) {
            float kv = kbf((float)j);
            acc += kv * cosf(2.0f * PI_F * (float)j * ((float)n - 160.0f) * (1.0f / 640.0f));
        }
        g_scale[n] = 1.0f / acc;
    }
    if (n < GQ) {
        float sn, cs;
        sincospif(-(float)n * (1.0f / 320.0f), &sn, &cs);   // -2*pi*n/640
        g_tw[n] = make_float2(cs, sn);
    }
}

__device__ __forceinline__ float2 cmul(float2 a, float2 b) {
    return make_float2(a.x * b.x - a.y * b.y, a.x * b.y + a.y * b.x);
}

// ---------------------------------------------------------------------------
// TWO 640-point forward FFTs per block phase. 640 = 5 * 128; 128 done as
// 3 composed radix-4 Stockham stages + 1 radix-2 stage, then twiddle +
// radix-5 combine. All smem indices bank-swizzled via SW().
// Abuf/Bbuf: [2][640]. Input in Abuf (A[f*640 + SW((cc%5)*128 + cc/5)]),
// natural-order output ends in Bbuf (read B[f*640 + SW(k)]).
// Requires blockDim.x == 320.
// ---------------------------------------------------------------------------
__device__ void fft640_pair(float2* Abuf, float2* Bbuf, const float2* tw, int t) {
    const int f  = (t >= 160) ? 1 : 0;        // warps 0-4 -> fft0, 5-9 -> fft1
    const int lt = t - 160 * f;               // 0..159
    const int n1 = lt >> 5;                   // sub-FFT 0..4
    const int u  = lt & 31;                   // butterfly index within sub-FFT
    float2* src = Abuf + f * 640;
    float2* dst = Bbuf + f * 640;

    #pragma unroll
    for (int c = 0; c < 3; c++) {
        const int sh = 2 * c;
        const int s  = 1 << sh;
        const int q  = u & (s - 1);
        const int pp = u >> sh;               // p' in [0, 32/s)
        const int br = (n1 << 7) + u;         // = n1*128 + q + s*p'
        float2 x0 = src[SW(br)];
        float2 x1 = src[SW(br + 64)];
        float2 x2 = src[SW(br + 32)];
        float2 x3 = src[SW(br + 96)];
        float2 w  = tw[(5 << sh) * pp];       // W_{2m}^{p'}
        float2 w2 = cmul(w, w);               // W_{m}^{p'}
        float2 A0 = make_float2(x0.x + x1.x, x0.y + x1.y);
        float2 d0 = make_float2(x0.x - x1.x, x0.y - x1.y);
        float2 A1 = cmul(d0, w);
        float2 B0 = make_float2(x2.x + x3.x, x2.y + x3.y);
        float2 d1 = make_float2(x2.x - x3.x, x2.y - x3.y);
        float2 t1 = cmul(d1, w);
        float2 B1 = make_float2(t1.y, -t1.x);            // -i * t1
        const int bw = (n1 << 7) + q + 4 * s * pp;
        float2 u2 = make_float2(A0.x - B0.x, A0.y - B0.y);
        float2 u3 = make_float2(A1.x - B1.x, A1.y - B1.y);
        dst[SW(bw)]         = make_float2(A0.x + B0.x, A0.y + B0.y);
        dst[SW(bw + s)]     = make_float2(A1.x + B1.x, A1.y + B1.y);
        dst[SW(bw + 2 * s)] = cmul(u2, w2);
        dst[SW(bw + 3 * s)] = cmul(u3, w2);
        __syncthreads();
        float2* tmp = src; src = dst; dst = tmp;
    }

    // final radix-2 stage (s=64, twiddle = 1): B -> A. Each thread does both ffts.
    {
        const int n1b = t / 64;               // t < 320 -> n1b 0..4
        const int qb  = t & 63;
        #pragma unroll
        for (int f2 = 0; f2 < 2; f2++) {
            float2* s2 = Bbuf + f2 * 640;     // after 3 composed stages data is in B
            float2* d2 = Abuf + f2 * 640;
            float2 a  = s2[SW((n1b << 7) + qb)];
            float2 b2 = s2[SW((n1b << 7) + qb + 64)];
            d2[SW((n1b << 7) + qb)]      = make_float2(a.x + b2.x, a.y + b2.y);
            d2[SW((n1b << 7) + qb + 64)] = make_float2(a.x - b2.x, a.y - b2.y);
        }
        __syncthreads();
    }

    // twiddle + radix-5 combine: A -> B (natural order). threads 0..255.
    // Twiddles tw[j*k2] computed as powers of tw[k2] (avoids conflicted loads).
    if (t < 256) {
        const int f5 = t >> 7;
        const int k2 = t & 127;
        const float2* s5 = Abuf + f5 * 640;
        float2* d5 = Bbuf + f5 * 640;
        float2 w1 = tw[k2];
        float2 w2 = cmul(w1, w1);
        float2 w3 = cmul(w2, w1);
        float2 w4 = cmul(w2, w2);
        float2 w5 = cmul(w3, w2);
        float2 g[5];
        g[0] = s5[SW(k2)];
        g[1] = cmul(s5[SW(128 + k2)], w1);
        g[2] = cmul(s5[SW(256 + k2)], w2);
        g[3] = cmul(s5[SW(384 + k2)], w3);
        g[4] = cmul(s5[SW(512 + k2)], w4);
        (void)w5;
        #pragma unroll
        for (int k1 = 0; k1 < 5; k1++) {
            float rx = 0.0f, ry = 0.0f;
            #pragma unroll
            for (int j = 0; j < 5; j++) {
                int id = (j * k1) % 5;
                rx += g[j].x * c5r[id] - g[j].y * c5i[id];
                ry += g[j].x * c5i[id] + g[j].y * c5r[id];
            }
            d5[SW((k1 << 7) + k2)] = make_float2(rx, ry);
        }
    }
    __syncthreads();
}

// ---------------------------------------------------------------------------
// Row pass: fused coil-multiply + apodization + pad + ifftshift + row FFT.
// 2 rows per block. grid = (160, 12), block = 320.
// ---------------------------------------------------------------------------
__global__ void __launch_bounds__(320) row_fft_kernel(
        const float* __restrict__ img_r, const float* __restrict__ img_i,
        const float* __restrict__ sm_r,  const float* __restrict__ sm_i) {
    __shared__ float2 A[2 * GQ];
    __shared__ float2 B[2 * GQ];
    __shared__ float2 tw[GQ];
    const int coil = blockIdx.y;
    const int pair = blockIdx.x;
    const int t = threadIdx.x;

    for (int k = t; k < GQ; k += 320) tw[k] = g_tw[k];

    #pragma unroll
    for (int f = 0; f < 2; f++) {
        int rr = pair * 2 + f;                         // 0..319
        int i  = (rr < 160) ? rr + 160 : rr - 160;     // source image row
        float si = g_scale[i];
        #pragma unroll
        for (int kk = 0; kk < 2; kk++) {
            int cc = t + kk * 320;
            float2 v = make_float2(0.0f, 0.0f);
            if (cc < 160 || cc >= 480) {
                int j = (cc < 160) ? cc + 160 : cc - 480;
                float ir  = img_r[i * NIMG + j];
                float ii  = img_i[i * NIMG + j];
                float sr  = sm_r[((size_t)coil * NIMG + i) * NIMG + j];
                float sim = sm_i[((size_t)coil * NIMG + i) * NIMG + j];
                float sc  = si * g_scale[j];
                v.x = (ir * sr - ii * sim) * sc;
                v.y = (ir * sim + ii * sr) * sc;
            }
            A[f * GQ + SW((cc % 5) * 128 + cc / 5)] = v;
        }
    }
    __syncthreads();
    fft640_pair(A, B, tw, t);
    #pragma unroll
    for (int f = 0; f < 2; f++) {
        int rr = pair * 2 + f;
        int r  = (rr < 160) ? rr : rr + 320;           // shifted grid row
        float2* gout = g_gridA + ((size_t)coil * GQ + r) * GQ;
        for (int k = t; k < GQ; k += 320) gout[k] = B[f * GQ + SW(k)];
    }
}

// ---------------------------------------------------------------------------
// Column pass: 4 columns per block staged through SMEM both directions
// (coalesced global loads AND stores). Writes g_gridB [coil][row][col] x 1/640.
// ---------------------------------------------------------------------------
#define COLS_PER_BLK 4
#define SPITCH 642
__global__ void __launch_bounds__(320) col_fft_kernel() {
    __shared__ float2 S[COLS_PER_BLK * SPITCH];
    __shared__ float2 A[2 * GQ];
    __shared__ float2 B[2 * GQ];
    __shared__ float2 tw[GQ];
    const int coil = blockIdx.y;
    const int c0 = blockIdx.x * COLS_PER_BLK;
    const int t = threadIdx.x;
    const float2* gin = g_gridA + (size_t)coil * GQ * GQ;

    for (int k = t; k < GQ; k += 320) tw[k] = g_tw[k];

    // load 320 nonzero rows; zero the middle 320
    for (int idx = t; idx < 320 * COLS_PER_BLK; idx += 320) {
        int rr = idx >> 2, col = idx & 3;
        int row = (rr < 160) ? rr : rr + 320;
        S[col * SPITCH + row]      = gin[(size_t)row * GQ + c0 + col];
        S[col * SPITCH + 160 + rr] = make_float2(0.0f, 0.0f);
    }
    __syncthreads();

    #pragma unroll
    for (int ph = 0; ph < 2; ph++) {
        #pragma unroll
        for (int f = 0; f < 2; f++) {
            int col = ph * 2 + f;
            for (int k = t; k < GQ; k += 320)
                A[f * GQ + SW((k % 5) * 128 + k / 5)] = S[col * SPITCH + k];
        }
        __syncthreads();
        fft640_pair(A, B, tw, t);
        #pragma unroll
        for (int f = 0; f < 2; f++) {
            int col = ph * 2 + f;
            for (int k = t; k < GQ; k += 320) {
                float2 v = B[f * GQ + SW(k)];
                S[col * SPITCH + k] = make_float2(v.x * INV_G, v.y * INV_G);
            }
        }
        __syncthreads();
    }

    float2* gout = g_gridB + (size_t)coil * GQ * GQ;
    for (int idx = t; idx < GQ * COLS_PER_BLK; idx += 320) {
        int row = idx >> 2, col = idx & 3;
        gout[(size_t)row * GQ + c0 + col] = S[col * SPITCH + row];
    }
}

// ---------------------------------------------------------------------------
// Transpose: g_gridB [coil][rc] -> g_gridC [rc][coil], coalesced both sides.
// ---------------------------------------------------------------------------
#define TRC 256
__global__ void __launch_bounds__(384) transpose_kernel() {
    __shared__ float2 T[TRC][NCOIL + 1];
    const int rc0 = blockIdx.x * TRC;
    for (int idx = threadIdx.x; idx < NCOIL * TRC; idx += 384) {
        int q = idx >> 8;           // / TRC
        int i = idx & (TRC - 1);
        T[i][q] = g_gridB[(size_t)q * (GQ * GQ) + rc0 + i];
    }
    __syncthreads();
    for (int idx = threadIdx.x; idx < TRC * NCOIL; idx += 384) {
        int i = idx / NCOIL;
        int q = idx - i * NCOIL;
        g_gridC[(size_t)(rc0 + i) * NCOIL + q] = T[i][q];
    }
}

// ---------------------------------------------------------------------------
// Interpolation: ONE WARP PER SAMPLE on coil-interleaved grid (R2 version).
// ---------------------------------------------------------------------------
#define WPB 8   // warps (samples) per block
__global__ void __launch_bounds__(32 * WPB) interp_kernel(const float* __restrict__ ktraj,
                                                          float* __restrict__ out) {
    __shared__ float2 s_part[WPB][72];
    __shared__ float2 s_out[NCOIL][WPB];
    const int warp = threadIdx.x >> 5;
    const int lane = threadIdx.x & 31;
    const int m = blockIdx.x * WPB + warp;

    float w = 0.0f;
    int   ki = 0;
    if (lane < 12) {
        int dim = lane >= 6 ? 1 : 0;
        int j   = lane - dim * 6;
        float om = ktraj[dim * MPTS + m];
        float tt = fmodf((om * 640.0f) / 6.2831855f, 640.0f);
        if (tt < 0.0f) tt += 640.0f;
        float base = floorf(tt);
        float k = base + (float)(j - 2);
        w = kbf(tt - k);
        ki = (int)k;
        if (ki < 0) ki += 640;
        else if (ki >= 640) ki -= 640;
    }

    const int e0 = lane, e1 = lane + 32, e2 = lane + 64;
    const int j0 = e0 / 12, j1 = e1 / 12;
    const int cc0 = e0 - j0 * 12, cc1 = e1 - j1 * 12, cc2 = e2 - 60;

    const unsigned FULL = 0xFFFFFFFFu;
    float wy0 = __shfl_sync(FULL, w, 6 + j0);
    float wy1 = __shfl_sync(FULL, w, 6 + j1);
    float wy2 = __shfl_sync(FULL, w, 11);
    int   iy0 = __shfl_sync(FULL, ki, 6 + j0);
    int   iy1 = __shfl_sync(FULL, ki, 6 + j1);
    int   iy2 = __shfl_sync(FULL, ki, 11);
    const int off0 = iy0 * NCOIL + cc0;
    const int off1 = iy1 * NCOIL + cc1;
    const int off2 = iy2 * NCOIL + cc2;
    const bool has2 = (lane < 8);

    float2 acc0 = make_float2(0.f, 0.f);
    float2 acc1 = make_float2(0.f, 0.f);
    float2 acc2 = make_float2(0.f, 0.f);

    #pragma unroll
    for (int i = 0; i < 6; i++) {
        float wx = __shfl_sync(FULL, w, i);
        int   ix = __shfl_sync(FULL, ki, i);
        const float2* __restrict__ rowp = g_gridC + (size_t)ix * (GQ * NCOIL);
        float2 v0 = __ldg(rowp + off0);
        float2 v1 = __ldg(rowp + off1);
        acc0.x += wx * v0.x; acc0.y += wx * v0.y;
        acc1.x += wx * v1.x; acc1.y += wx * v1.y;
        if (has2) {
            float2 v2 = __ldg(rowp + off2);
            acc2.x += wx * v2.x; acc2.y += wx * v2.y;
        }
    }

    s_part[warp][e0] = make_float2(wy0 * acc0.x, wy0 * acc0.y);
    s_part[warp][e1] = make_float2(wy1 * acc1.x, wy1 * acc1.y);
    if (has2) s_part[warp][e2] = make_float2(wy2 * acc2.x, wy2 * acc2.y);
    __syncwarp();

    if (lane < 12) {
        float rx = 0.f, ry = 0.f;
        #pragma unroll
        for (int j = 0; j < 6; j++) {
            float2 p = s_part[warp][j * 12 + lane];
            rx += p.x; ry += p.y;
        }
        s_out[lane][warp] = make_float2(rx, ry);
    }
    __syncthreads();

    if (threadIdx.x < NCOIL * WPB) {
        int c = threadIdx.x >> 3;
        int s = threadIdx.x & 7;
        ((float2*)out)[(size_t)c * MPTS + blockIdx.x * WPB + s] = s_out[c][s];
    }
}

// ---------------------------------------------------------------------------
extern "C" void kernel_launch(void* const* d_in, const int* in_sizes, int n_in,
                              void* d_out, int out_size) {
    const float* img_r = (const float*)d_in[0];
    const float* img_i = (const float*)d_in[1];
    const float* sm_r  = (const float*)d_in[2];
    const float* sm_i  = (const float*)d_in[3];
    const float* kt    = (const float*)d_in[4];
    float* out = (float*)d_out;

    apod_kernel<<<1, 640>>>();
    row_fft_kernel<<<dim3(160, NCOIL), 320>>>(img_r, img_i, sm_r, sm_i);
    col_fft_kernel<<<dim3(GQ / COLS_PER_BLK, NCOIL), 320>>>();
    transpose_kernel<<<(GQ * GQ) / TRC, 384>>>();
    interp_kernel<<<MPTS / WPB, 32 * WPB>>>(kt, out);
}

// round 10
// speedup vs baseline: 1.1992x; 1.0390x over previous
#include <cuda_runtime.h>
#include <cstdint>

#define GQ     640
#define NIMG   320
#define NCOIL  12
#define MPTS   102400
#define PI_F   3.14159265358979f
#define BETA_F 13.855101f      // pi * sqrt((6*1.5/2)^2 - 0.8)
#define INV_G  0.0015625f      // 1/640

// Bank swizzle for the FFT smem buffers (float2 elements).
#define SW(i) ((i) ^ (((i) >> 4) & 3))

// Scratch (zero-initialized at module load).
__device__ float2 g_gridA[NCOIL * GQ * GQ];                 // [coil][row][col]
__device__ float2 g_gridB[NCOIL * GQ * GQ];                 // [coil][row][col] after col FFT
__device__ __align__(16) float2 g_gridC[GQ * GQ * NCOIL];   // [row][col][coil]
__device__ float  g_scale[NIMG];
__device__ float2 g_tw[GQ];                                 // exp(-2*pi*i*k/640)

__constant__ float c5r[5] = {1.0f, 0.30901699f, -0.80901699f, -0.80901699f, 0.30901699f};
__constant__ float c5i[5] = {0.0f, -0.95105652f, -0.58778525f, 0.58778525f, 0.95105652f};

// ---------------------------------------------------------------------------
// Modified Bessel I0 (Abramowitz & Stegun, ~2e-7 rel error)
// ---------------------------------------------------------------------------
__device__ __forceinline__ float i0f_dev(float x) {
    if (x < 3.75f) {
        float t = x * (1.0f / 3.75f);
        t *= t;
        return 1.0f + t * (3.5156229f + t * (3.0899424f + t * (1.2067492f
             + t * (0.2659732f + t * (0.0360768f + t * 0.0045813f)))));
    } else {
        float t = 3.75f / x;
        float p = 0.39894228f + t * (0.01328592f + t * (0.00225319f + t * (-0.00157565f
                + t * (0.00916281f + t * (-0.02057706f + t * (0.02635537f
                + t * (-0.01647633f + t * 0.00392377f)))))));
        return expf(x) * rsqrtf(x) * p;
    }
}

// Kaiser-Bessel kernel, support |u| <= 3 (J=6)
__device__ __forceinline__ float kbf(float u) {
    float m = fabsf(u) * (1.0f / 3.0f);
    float a = 1.0f - m * m;
    a = a > 0.0f ? a : 0.0f;
    float v = i0f_dev(BETA_F * sqrtf(a)) * (1.0f / 6.0f);
    return (m <= 1.0f) ? v : 0.0f;
}

// ---------------------------------------------------------------------------
// Apodization scale (length 320) + twiddle table (length 640). block = 640.
// ---------------------------------------------------------------------------
__global__ void apod_kernel() {
    int n = threadIdx.x;
    if (n < NIMG) {
        float acc = 0.0f;
        #pragma unroll
        for (int j = -6; j <= 6; j++) {
            float kv = kbf((float)j);
            acc += kv * cosf(2.0f * PI_F * (float)j * ((float)n - 160.0f) * (1.0f / 640.0f));
        }
        g_scale[n] = 1.0f / acc;
    }
    if (n < GQ) {
        float sn, cs;
        sincospif(-(float)n * (1.0f / 320.0f), &sn, &cs);   // -2*pi*n/640
        g_tw[n] = make_float2(cs, sn);
    }
}

__device__ __forceinline__ float2 cmul(float2 a, float2 b) {
    return make_float2(a.x * b.x - a.y * b.y, a.x * b.y + a.y * b.x);
}

// ---------------------------------------------------------------------------
// TWO 640-point forward FFTs per block phase (radix-4 Stockham + radix-2 +
// radix-5, bank-swizzled). blockDim.x == 320.
// ---------------------------------------------------------------------------
__device__ void fft640_pair(float2* Abuf, float2* Bbuf, const float2* tw, int t) {
    const int f  = (t >= 160) ? 1 : 0;
    const int lt = t - 160 * f;
    const int n1 = lt >> 5;
    const int u  = lt & 31;
    float2* src = Abuf + f * 640;
    float2* dst = Bbuf + f * 640;

    #pragma unroll
    for (int c = 0; c < 3; c++) {
        const int sh = 2 * c;
        const int s  = 1 << sh;
        const int q  = u & (s - 1);
        const int pp = u >> sh;
        const int br = (n1 << 7) + u;
        float2 x0 = src[SW(br)];
        float2 x1 = src[SW(br + 64)];
        float2 x2 = src[SW(br + 32)];
        float2 x3 = src[SW(br + 96)];
        float2 w  = tw[(5 << sh) * pp];
        float2 w2 = cmul(w, w);
        float2 A0 = make_float2(x0.x + x1.x, x0.y + x1.y);
        float2 d0 = make_float2(x0.x - x1.x, x0.y - x1.y);
        float2 A1 = cmul(d0, w);
        float2 B0 = make_float2(x2.x + x3.x, x2.y + x3.y);
        float2 d1 = make_float2(x2.x - x3.x, x2.y - x3.y);
        float2 t1 = cmul(d1, w);
        float2 B1 = make_float2(t1.y, -t1.x);
        const int bw = (n1 << 7) + q + 4 * s * pp;
        float2 u2 = make_float2(A0.x - B0.x, A0.y - B0.y);
        float2 u3 = make_float2(A1.x - B1.x, A1.y - B1.y);
        dst[SW(bw)]         = make_float2(A0.x + B0.x, A0.y + B0.y);
        dst[SW(bw + s)]     = make_float2(A1.x + B1.x, A1.y + B1.y);
        dst[SW(bw + 2 * s)] = cmul(u2, w2);
        dst[SW(bw + 3 * s)] = cmul(u3, w2);
        __syncthreads();
        float2* tmp = src; src = dst; dst = tmp;
    }

    {
        const int n1b = t / 64;
        const int qb  = t & 63;
        #pragma unroll
        for (int f2 = 0; f2 < 2; f2++) {
            float2* s2 = Bbuf + f2 * 640;
            float2* d2 = Abuf + f2 * 640;
            float2 a  = s2[SW((n1b << 7) + qb)];
            float2 b2 = s2[SW((n1b << 7) + qb + 64)];
            d2[SW((n1b << 7) + qb)]      = make_float2(a.x + b2.x, a.y + b2.y);
            d2[SW((n1b << 7) + qb + 64)] = make_float2(a.x - b2.x, a.y - b2.y);
        }
        __syncthreads();
    }

    if (t < 256) {
        const int f5 = t >> 7;
        const int k2 = t & 127;
        const float2* s5 = Abuf + f5 * 640;
        float2* d5 = Bbuf + f5 * 640;
        float2 w1 = tw[k2];
        float2 w2 = cmul(w1, w1);
        float2 w3 = cmul(w2, w1);
        float2 w4 = cmul(w2, w2);
        float2 g[5];
        g[0] = s5[SW(k2)];
        g[1] = cmul(s5[SW(128 + k2)], w1);
        g[2] = cmul(s5[SW(256 + k2)], w2);
        g[3] = cmul(s5[SW(384 + k2)], w3);
        g[4] = cmul(s5[SW(512 + k2)], w4);
        #pragma unroll
        for (int k1 = 0; k1 < 5; k1++) {
            float rx = 0.0f, ry = 0.0f;
            #pragma unroll
            for (int j = 0; j < 5; j++) {
                int id = (j * k1) % 5;
                rx += g[j].x * c5r[id] - g[j].y * c5i[id];
                ry += g[j].x * c5i[id] + g[j].y * c5r[id];
            }
            d5[SW((k1 << 7) + k2)] = make_float2(rx, ry);
        }
    }
    __syncthreads();
}

// ---------------------------------------------------------------------------
// Row pass: fused coil-multiply + apodization + pad + ifftshift + row FFT.
// ---------------------------------------------------------------------------
__global__ void __launch_bounds__(320) row_fft_kernel(
        const float* __restrict__ img_r, const float* __restrict__ img_i,
        const float* __restrict__ sm_r,  const float* __restrict__ sm_i) {
    __shared__ float2 A[2 * GQ];
    __shared__ float2 B[2 * GQ];
    __shared__ float2 tw[GQ];
    const int coil = blockIdx.y;
    const int pair = blockIdx.x;
    const int t = threadIdx.x;

    for (int k = t; k < GQ; k += 320) tw[k] = g_tw[k];

    #pragma unroll
    for (int f = 0; f < 2; f++) {
        int rr = pair * 2 + f;
        int i  = (rr < 160) ? rr + 160 : rr - 160;
        float si = g_scale[i];
        #pragma unroll
        for (int kk = 0; kk < 2; kk++) {
            int cc = t + kk * 320;
            float2 v = make_float2(0.0f, 0.0f);
            if (cc < 160 || cc >= 480) {
                int j = (cc < 160) ? cc + 160 : cc - 480;
                float ir  = img_r[i * NIMG + j];
                float ii  = img_i[i * NIMG + j];
                float sr  = sm_r[((size_t)coil * NIMG + i) * NIMG + j];
                float sim = sm_i[((size_t)coil * NIMG + i) * NIMG + j];
                float sc  = si * g_scale[j];
                v.x = (ir * sr - ii * sim) * sc;
                v.y = (ir * sim + ii * sr) * sc;
            }
            A[f * GQ + SW((cc % 5) * 128 + cc / 5)] = v;
        }
    }
    __syncthreads();
    fft640_pair(A, B, tw, t);
    #pragma unroll
    for (int f = 0; f < 2; f++) {
        int rr = pair * 2 + f;
        int r  = (rr < 160) ? rr : rr + 320;
        float2* gout = g_gridA + ((size_t)coil * GQ + r) * GQ;
        for (int k = t; k < GQ; k += 320) gout[k] = B[f * GQ + SW(k)];
    }
}

// ---------------------------------------------------------------------------
// Column pass: 4 columns per block, smem-staged both directions.
// ---------------------------------------------------------------------------
#define COLS_PER_BLK 4
#define SPITCH 642
__global__ void __launch_bounds__(320) col_fft_kernel() {
    __shared__ float2 S[COLS_PER_BLK * SPITCH];
    __shared__ float2 A[2 * GQ];
    __shared__ float2 B[2 * GQ];
    __shared__ float2 tw[GQ];
    const int coil = blockIdx.y;
    const int c0 = blockIdx.x * COLS_PER_BLK;
    const int t = threadIdx.x;
    const float2* gin = g_gridA + (size_t)coil * GQ * GQ;

    for (int k = t; k < GQ; k += 320) tw[k] = g_tw[k];

    for (int idx = t; idx < 320 * COLS_PER_BLK; idx += 320) {
        int rr = idx >> 2, col = idx & 3;
        int row = (rr < 160) ? rr : rr + 320;
        S[col * SPITCH + row]      = gin[(size_t)row * GQ + c0 + col];
        S[col * SPITCH + 160 + rr] = make_float2(0.0f, 0.0f);
    }
    __syncthreads();

    #pragma unroll
    for (int ph = 0; ph < 2; ph++) {
        #pragma unroll
        for (int f = 0; f < 2; f++) {
            int col = ph * 2 + f;
            for (int k = t; k < GQ; k += 320)
                A[f * GQ + SW((k % 5) * 128 + k / 5)] = S[col * SPITCH + k];
        }
        __syncthreads();
        fft640_pair(A, B, tw, t);
        #pragma unroll
        for (int f = 0; f < 2; f++) {
            int col = ph * 2 + f;
            for (int k = t; k < GQ; k += 320) {
                float2 v = B[f * GQ + SW(k)];
                S[col * SPITCH + k] = make_float2(v.x * INV_G, v.y * INV_G);
            }
        }
        __syncthreads();
    }

    float2* gout = g_gridB + (size_t)coil * GQ * GQ;
    for (int idx = t; idx < GQ * COLS_PER_BLK; idx += 320) {
        int row = idx >> 2, col = idx & 3;
        gout[(size_t)row * GQ + c0 + col] = S[col * SPITCH + row];
    }
}

// ---------------------------------------------------------------------------
// Transpose: g_gridB [coil][rc] -> g_gridC [rc][coil] (float2, same as R5),
// vectorized: float4 loads (2 grid points) and float4 stores (2 coils).
// Block: 256 threads, 128 rc per block.
// ---------------------------------------------------------------------------
#define TRC2 128
__global__ void __launch_bounds__(256) transpose_kernel() {
    __shared__ float2 T[TRC2][NCOIL + 1];
    const int rc0 = blockIdx.x * TRC2;
    const int t = threadIdx.x;

    // load: 12 coils x 64 float4 (= 128 rc) = 768 float4 per block
    #pragma unroll
    for (int k = 0; k < 3; k++) {
        int idx = t + k * 256;
        int q = idx >> 6;                 // coil 0..11
        int i = idx & 63;                 // float4 index -> rc pair (2i, 2i+1)
        const float4* src = (const float4*)(g_gridB + (size_t)q * (GQ * GQ) + rc0);
        float4 v = src[i];
        T[2 * i][q]     = make_float2(v.x, v.y);
        T[2 * i + 1][q] = make_float2(v.z, v.w);
    }
    __syncthreads();

    // store: 128 rc x 6 coil-pairs = 768 float4 per block (fully contiguous)
    float4* dst = (float4*)(g_gridC + (size_t)rc0 * NCOIL);
    #pragma unroll
    for (int k = 0; k < 3; k++) {
        int idx = t + k * 256;
        int rc = idx / 6;                 // 0..127
        int j  = idx - rc * 6;            // coil pair 0..5
        float2 a = T[rc][2 * j];
        float2 b = T[rc][2 * j + 1];
        dst[idx] = make_float4(a.x, a.y, b.x, b.y);
    }
}

// ---------------------------------------------------------------------------
// Interpolation: ONE WARP PER SAMPLE on coil-interleaved float2 grid
// (byte-identical to the R5-passing version).
// ---------------------------------------------------------------------------
#define WPB 8   // warps (samples) per block
__global__ void __launch_bounds__(32 * WPB) interp_kernel(const float* __restrict__ ktraj,
                                                          float* __restrict__ out) {
    __shared__ float2 s_part[WPB][72];
    __shared__ float2 s_out[NCOIL][WPB];
    const int warp = threadIdx.x >> 5;
    const int lane = threadIdx.x & 31;
    const int m = blockIdx.x * WPB + warp;

    float w = 0.0f;
    int   ki = 0;
    if (lane < 12) {
        int dim = lane >= 6 ? 1 : 0;
        int j   = lane - dim * 6;
        float om = ktraj[dim * MPTS + m];
        float tt = fmodf((om * 640.0f) / 6.2831855f, 640.0f);
        if (tt < 0.0f) tt += 640.0f;
        float base = floorf(tt);
        float k = base + (float)(j - 2);
        w = kbf(tt - k);
        ki = (int)k;
        if (ki < 0) ki += 640;
        else if (ki >= 640) ki -= 640;
    }

    const int e0 = lane, e1 = lane + 32, e2 = lane + 64;
    const int j0 = e0 / 12, j1 = e1 / 12;
    const int cc0 = e0 - j0 * 12, cc1 = e1 - j1 * 12, cc2 = e2 - 60;

    const unsigned FULL = 0xFFFFFFFFu;
    float wy0 = __shfl_sync(FULL, w, 6 + j0);
    float wy1 = __shfl_sync(FULL, w, 6 + j1);
    float wy2 = __shfl_sync(FULL, w, 11);
    int   iy0 = __shfl_sync(FULL, ki, 6 + j0);
    int   iy1 = __shfl_sync(FULL, ki, 6 + j1);
    int   iy2 = __shfl_sync(FULL, ki, 11);
    const int off0 = iy0 * NCOIL + cc0;
    const int off1 = iy1 * NCOIL + cc1;
    const int off2 = iy2 * NCOIL + cc2;
    const bool has2 = (lane < 8);

    float2 acc0 = make_float2(0.f, 0.f);
    float2 acc1 = make_float2(0.f, 0.f);
    float2 acc2 = make_float2(0.f, 0.f);

    #pragma unroll
    for (int i = 0; i < 6; i++) {
        float wx = __shfl_sync(FULL, w, i);
        int   ix = __shfl_sync(FULL, ki, i);
        const float2* __restrict__ rowp = g_gridC + (size_t)ix * (GQ * NCOIL);
        float2 v0 = __ldg(rowp + off0);
        float2 v1 = __ldg(rowp + off1);
        acc0.x += wx * v0.x; acc0.y += wx * v0.y;
        acc1.x += wx * v1.x; acc1.y += wx * v1.y;
        if (has2) {
            float2 v2 = __ldg(rowp + off2);
            acc2.x += wx * v2.x; acc2.y += wx * v2.y;
        }
    }

    s_part[warp][e0] = make_float2(wy0 * acc0.x, wy0 * acc0.y);
    s_part[warp][e1] = make_float2(wy1 * acc1.x, wy1 * acc1.y);
    if (has2) s_part[warp][e2] = make_float2(wy2 * acc2.x, wy2 * acc2.y);
    __syncwarp();

    if (lane < 12) {
        float rx = 0.f, ry = 0.f;
        #pragma unroll
        for (int j = 0; j < 6; j++) {
            float2 p = s_part[warp][j * 12 + lane];
            rx += p.x; ry += p.y;
        }
        s_out[lane][warp] = make_float2(rx, ry);
    }
    __syncthreads();

    if (threadIdx.x < NCOIL * WPB) {
        int c = threadIdx.x >> 3;
        int s = threadIdx.x & 7;
        ((float2*)out)[(size_t)c * MPTS + blockIdx.x * WPB + s] = s_out[c][s];
    }
}

// ---------------------------------------------------------------------------
extern "C" void kernel_launch(void* const* d_in, const int* in_sizes, int n_in,
                              void* d_out, int out_size) {
    const float* img_r = (const float*)d_in[0];
    const float* img_i = (const float*)d_in[1];
    const float* sm_r  = (const float*)d_in[2];
    const float* sm_i  = (const float*)d_in[3];
    const float* kt    = (const float*)d_in[4];
    float* out = (float*)d_out;

    apod_kernel<<<1, 640>>>();
    row_fft_kernel<<<dim3(160, NCOIL), 320>>>(img_r, img_i, sm_r, sm_i);
    col_fft_kernel<<<dim3(GQ / COLS_PER_BLK, NCOIL), 320>>>();
    transpose_kernel<<<(GQ * GQ) / TRC2, 256>>>();
    interp_kernel<<<MPTS / WPB, 32 * WPB>>>(kt, out);
}

// round 11
// speedup vs baseline: 1.3727x; 1.1448x over previous
#include <cuda_runtime.h>
#include <cstdint>

#define GQ     640
#define NIMG   320
#define NCOIL  12
#define MPTS   102400
#define PI_F   3.14159265358979f
#define BETA_F 13.855101f      // pi * sqrt((6*1.5/2)^2 - 0.8)
#define INV_G  0.0015625f      // 1/640

// Per-boundary bank swizzles (float2 elements).
#define SW1(i) ((i) ^ (((i) >> 4) & 3))          // stage0->1 and stage2->r5 layouts
#define SW2(i) ((i) ^ ((((i) >> 4) & 3) << 2))   // stage1->2 layout

// Scratch (zero-initialized at module load).
__device__ float2 g_gridA[NCOIL * GQ * GQ];                 // [coil][row][col]
__device__ float2 g_gridB[NCOIL * GQ * GQ];                 // [coil][row][col] after col FFT
__device__ __align__(16) float2 g_gridC[GQ * GQ * NCOIL];   // [row][col][coil]
__device__ float  g_scale[NIMG];
__device__ float2 g_tw[GQ];                                 // exp(-2*pi*i*k/640)

__constant__ float c5r[5] = {1.0f, 0.30901699f, -0.80901699f, -0.80901699f, 0.30901699f};
__constant__ float c5i[5] = {0.0f, -0.95105652f, -0.58778525f, 0.58778525f, 0.95105652f};

// ---------------------------------------------------------------------------
// Modified Bessel I0 (Abramowitz & Stegun, ~2e-7 rel error)
// ---------------------------------------------------------------------------
__device__ __forceinline__ float i0f_dev(float x) {
    if (x < 3.75f) {
        float t = x * (1.0f / 3.75f);
        t *= t;
        return 1.0f + t * (3.5156229f + t * (3.0899424f + t * (1.2067492f
             + t * (0.2659732f + t * (0.0360768f + t * 0.0045813f)))));
    } else {
        float t = 3.75f / x;
        float p = 0.39894228f + t * (0.01328592f + t * (0.00225319f + t * (-0.00157565f
                + t * (0.00916281f + t * (-0.02057706f + t * (0.02635537f
                + t * (-0.01647633f + t * 0.00392377f)))))));
        return expf(x) * rsqrtf(x) * p;
    }
}

// Kaiser-Bessel kernel, support |u| <= 3 (J=6)
__device__ __forceinline__ float kbf(float u) {
    float m = fabsf(u) * (1.0f / 3.0f);
    float a = 1.0f - m * m;
    a = a > 0.0f ? a : 0.0f;
    float v = i0f_dev(BETA_F * sqrtf(a)) * (1.0f / 6.0f);
    return (m <= 1.0f) ? v : 0.0f;
}

// ---------------------------------------------------------------------------
// Apodization scale (length 320) + twiddle table (length 640). block = 640.
// ---------------------------------------------------------------------------
__global__ void apod_kernel() {
    int n = threadIdx.x;
    if (n < NIMG) {
        float acc = 0.0f;
        #pragma unroll
        for (int j = -6; j <= 6; j++) {
            float kv = kbf((float)j);
            acc += kv * cosf(2.0f * PI_F * (float)j * ((float)n - 160.0f) * (1.0f / 640.0f));
        }
        g_scale[n] = 1.0f / acc;
    }
    if (n < GQ) {
        float sn, cs;
        sincospif(-(float)n * (1.0f / 320.0f), &sn, &cs);   // -2*pi*n/640
        g_tw[n] = make_float2(cs, sn);
    }
}

__device__ __forceinline__ float2 cmul(float2 a, float2 b) {
    return make_float2(a.x * b.x - a.y * b.y, a.x * b.y + a.y * b.x);
}

// ---------------------------------------------------------------------------
// TWO 640-point forward FFTs per call. 640 = 5 * 128; 128 = three composed
// radix-4 Stockham stages + radix-2 (fused into the radix-5 combine).
// Inputs in0/in1: NATURAL-order float2[640] arrays (may alias Wa halves).
// Wa/Wb: work buffers float2[2*640]. Outputs out0/out1: natural order,
// scaled by outScale (global or smem). blockDim.x == 320.
// NOTE: no trailing __syncthreads(); caller adds one if buffers are reused.
// ---------------------------------------------------------------------------
__device__ void fft640_v2(const float2* in0, const float2* in1,
                          float2* Wa, float2* Wb, const float2* tw, int t,
                          float2* out0, float2* out1, float outScale) {
    const int f  = (t >= 160) ? 1 : 0;
    const int lt = t - 160 * f;
    const int n1 = lt >> 5;
    const int u  = lt & 31;
    const float2* in = f ? in1 : in0;
    float2* A = Wa + f * 640;
    float2* B = Wb + f * 640;

    // ---- stage 0 (s=1): natural in -> B (SW1) ----
    {
        float2 x0 = in[5 * u + n1];
        float2 x1 = in[5 * (u + 64) + n1];
        float2 x2 = in[5 * (u + 32) + n1];
        float2 x3 = in[5 * (u + 96) + n1];
        float2 w  = tw[5 * u];
        float2 w2 = cmul(w, w);
        float2 A0 = make_float2(x0.x + x1.x, x0.y + x1.y);
        float2 d0 = make_float2(x0.x - x1.x, x0.y - x1.y);
        float2 A1 = cmul(d0, w);
        float2 B0 = make_float2(x2.x + x3.x, x2.y + x3.y);
        float2 d1 = make_float2(x2.x - x3.x, x2.y - x3.y);
        float2 t1 = cmul(d1, w);
        float2 B1 = make_float2(t1.y, -t1.x);                // -i * t1
        const int bw = (n1 << 7) + 4 * u;
        float2 u2 = make_float2(A0.x - B0.x, A0.y - B0.y);
        float2 u3 = make_float2(A1.x - B1.x, A1.y - B1.y);
        B[SW1(bw)]     = make_float2(A0.x + B0.x, A0.y + B0.y);
        B[SW1(bw + 1)] = make_float2(A1.x + B1.x, A1.y + B1.y);
        B[SW1(bw + 2)] = cmul(u2, w2);
        B[SW1(bw + 3)] = cmul(u3, w2);
    }
    __syncthreads();

    // ---- stage 1 (s=4): B (SW1) -> A (SW2) ----
    {
        const int q  = u & 3;
        const int pp = u >> 2;
        const int br = (n1 << 7) + u;
        float2 x0 = B[SW1(br)];
        float2 x1 = B[SW1(br + 64)];
        float2 x2 = B[SW1(br + 32)];
        float2 x3 = B[SW1(br + 96)];
        float2 w  = tw[20 * pp];
        float2 w2 = cmul(w, w);
        float2 A0 = make_float2(x0.x + x1.x, x0.y + x1.y);
        float2 d0 = make_float2(x0.x - x1.x, x0.y - x1.y);
        float2 A1 = cmul(d0, w);
        float2 B0 = make_float2(x2.x + x3.x, x2.y + x3.y);
        float2 d1 = make_float2(x2.x - x3.x, x2.y - x3.y);
        float2 t1 = cmul(d1, w);
        float2 B1 = make_float2(t1.y, -t1.x);
        const int bw = (n1 << 7) + q + 16 * pp;
        float2 u2 = make_float2(A0.x - B0.x, A0.y - B0.y);
        float2 u3 = make_float2(A1.x - B1.x, A1.y - B1.y);
        A[SW2(bw)]      = make_float2(A0.x + B0.x, A0.y + B0.y);
        A[SW2(bw + 4)]  = make_float2(A1.x + B1.x, A1.y + B1.y);
        A[SW2(bw + 8)]  = cmul(u2, w2);
        A[SW2(bw + 12)] = cmul(u3, w2);
    }
    __syncthreads();

    // ---- stage 2 (s=16): A (SW2) -> B (SW1) ----
    {
        const int q  = u & 15;
        const int pp = u >> 4;
        const int br = (n1 << 7) + u;
        float2 x0 = A[SW2(br)];
        float2 x1 = A[SW2(br + 64)];
        float2 x2 = A[SW2(br + 32)];
        float2 x3 = A[SW2(br + 96)];
        float2 w  = tw[80 * pp];
        float2 w2 = cmul(w, w);
        float2 A0 = make_float2(x0.x + x1.x, x0.y + x1.y);
        float2 d0 = make_float2(x0.x - x1.x, x0.y - x1.y);
        float2 A1 = cmul(d0, w);
        float2 B0 = make_float2(x2.x + x3.x, x2.y + x3.y);
        float2 d1 = make_float2(x2.x - x3.x, x2.y - x3.y);
        float2 t1 = cmul(d1, w);
        float2 B1 = make_float2(t1.y, -t1.x);
        const int bw = (n1 << 7) + q + 64 * pp;
        float2 u2 = make_float2(A0.x - B0.x, A0.y - B0.y);
        float2 u3 = make_float2(A1.x - B1.x, A1.y - B1.y);
        B[SW1(bw)]      = make_float2(A0.x + B0.x, A0.y + B0.y);
        B[SW1(bw + 16)] = make_float2(A1.x + B1.x, A1.y + B1.y);
        B[SW1(bw + 32)] = cmul(u2, w2);
        B[SW1(bw + 48)] = cmul(u3, w2);
    }
    __syncthreads();

    // ---- fused radix-2 + twiddle + radix-5: B (SW1) -> out (natural) ----
    if (t < 256) {
        const int f5  = t >> 7;
        const int k2  = t & 127;
        const int k2l = k2 & 63;
        const float2* Bf = Wb + f5 * 640;
        float2* out = f5 ? out1 : out0;
        float2 w1 = tw[k2];
        float2 w2 = cmul(w1, w1);
        float2 w3 = cmul(w2, w1);
        float2 w4 = cmul(w2, w2);
        float2 g[5];
        #pragma unroll
        for (int j = 0; j < 5; j++) {
            float2 lo = Bf[SW1((j << 7) + k2l)];
            float2 hi = Bf[SW1((j << 7) + k2l + 64)];
            float2 pre = (k2 < 64)
                ? make_float2(lo.x + hi.x, lo.y + hi.y)
                : make_float2(lo.x - hi.x, lo.y - hi.y);
            g[j] = pre;
        }
        g[1] = cmul(g[1], w1);
        g[2] = cmul(g[2], w2);
        g[3] = cmul(g[3], w3);
        g[4] = cmul(g[4], w4);
        #pragma unroll
        for (int k1 = 0; k1 < 5; k1++) {
            float rx = 0.0f, ry = 0.0f;
            #pragma unroll
            for (int j = 0; j < 5; j++) {
                int id = (j * k1) % 5;
                rx += g[j].x * c5r[id] - g[j].y * c5i[id];
                ry += g[j].x * c5i[id] + g[j].y * c5r[id];
            }
            out[(k1 << 7) + k2] = make_float2(rx * outScale, ry * outScale);
        }
    }
}

// ---------------------------------------------------------------------------
// Row pass: fused coil-multiply + apodization + pad + ifftshift + row FFT.
// 2 rows per block; FFT output stored directly to global (coalesced).
// ---------------------------------------------------------------------------
__global__ void __launch_bounds__(320) row_fft_kernel(
        const float* __restrict__ img_r, const float* __restrict__ img_i,
        const float* __restrict__ sm_r,  const float* __restrict__ sm_i) {
    __shared__ float2 Wa[2 * GQ];
    __shared__ float2 Wb[2 * GQ];
    __shared__ float2 tw[GQ];
    const int coil = blockIdx.y;
    const int pair = blockIdx.x;
    const int t = threadIdx.x;

    for (int k = t; k < GQ; k += 320) tw[k] = g_tw[k];

    #pragma unroll
    for (int f = 0; f < 2; f++) {
        int rr = pair * 2 + f;
        int i  = (rr < 160) ? rr + 160 : rr - 160;
        float si = g_scale[i];
        #pragma unroll
        for (int kk = 0; kk < 2; kk++) {
            int cc = t + kk * 320;
            float2 v = make_float2(0.0f, 0.0f);
            if (cc < 160 || cc >= 480) {
                int j = (cc < 160) ? cc + 160 : cc - 480;
                float ir  = img_r[i * NIMG + j];
                float ii  = img_i[i * NIMG + j];
                float sr  = sm_r[((size_t)coil * NIMG + i) * NIMG + j];
                float sim = sm_i[((size_t)coil * NIMG + i) * NIMG + j];
                float sc  = si * g_scale[j];
                v.x = (ir * sr - ii * sim) * sc;
                v.y = (ir * sim + ii * sr) * sc;
            }
            Wa[f * GQ + cc] = v;                      // natural order
        }
    }
    __syncthreads();

    int rr0 = pair * 2, rr1 = pair * 2 + 1;
    int r0 = (rr0 < 160) ? rr0 : rr0 + 320;
    int r1 = (rr1 < 160) ? rr1 : rr1 + 320;
    float2* gout0 = g_gridA + ((size_t)coil * GQ + r0) * GQ;
    float2* gout1 = g_gridA + ((size_t)coil * GQ + r1) * GQ;
    fft640_v2(Wa, Wa + GQ, Wa, Wb, tw, t, gout0, gout1, 1.0f);
}

// ---------------------------------------------------------------------------
// Column pass: 4 columns per block staged through SMEM. FFT reads the
// staging buffer S directly (natural order) and writes back into S scaled;
// final copy to gridB is coalesced.
// ---------------------------------------------------------------------------
#define COLS_PER_BLK 4
#define SPITCH 642
__global__ void __launch_bounds__(320) col_fft_kernel() {
    __shared__ float2 S[COLS_PER_BLK * SPITCH];
    __shared__ float2 Wa[2 * GQ];
    __shared__ float2 Wb[2 * GQ];
    __shared__ float2 tw[GQ];
    const int coil = blockIdx.y;
    const int c0 = blockIdx.x * COLS_PER_BLK;
    const int t = threadIdx.x;
    const float2* gin = g_gridA + (size_t)coil * GQ * GQ;

    for (int k = t; k < GQ; k += 320) tw[k] = g_tw[k];

    // load 320 nonzero rows; zero the middle 320
    for (int idx = t; idx < 320 * COLS_PER_BLK; idx += 320) {
        int rr = idx >> 2, col = idx & 3;
        int row = (rr < 160) ? rr : rr + 320;
        S[col * SPITCH + row]      = gin[(size_t)row * GQ + c0 + col];
        S[col * SPITCH + 160 + rr] = make_float2(0.0f, 0.0f);
    }
    __syncthreads();

    #pragma unroll
    for (int ph = 0; ph < 2; ph++) {
        float2* s0 = S + (ph * 2) * SPITCH;
        float2* s1 = S + (ph * 2 + 1) * SPITCH;
        fft640_v2(s0, s1, Wa, Wb, tw, t, s0, s1, INV_G);
        __syncthreads();
    }

    float2* gout = g_gridB + (size_t)coil * GQ * GQ;
    for (int idx = t; idx < GQ * COLS_PER_BLK; idx += 320) {
        int row = idx >> 2, col = idx & 3;
        gout[(size_t)row * GQ + c0 + col] = S[col * SPITCH + row];
    }
}

// ---------------------------------------------------------------------------
// Transpose: g_gridB [coil][rc] -> g_gridC [rc][coil], float4 both sides.
// ---------------------------------------------------------------------------
#define TRC2 128
__global__ void __launch_bounds__(256) transpose_kernel() {
    __shared__ float2 T[TRC2][NCOIL + 1];
    const int rc0 = blockIdx.x * TRC2;
    const int t = threadIdx.x;

    #pragma unroll
    for (int k = 0; k < 3; k++) {
        int idx = t + k * 256;
        int q = idx >> 6;
        int i = idx & 63;
        const float4* src = (const float4*)(g_gridB + (size_t)q * (GQ * GQ) + rc0);
        float4 v = src[i];
        T[2 * i][q]     = make_float2(v.x, v.y);
        T[2 * i + 1][q] = make_float2(v.z, v.w);
    }
    __syncthreads();

    float4* dst = (float4*)(g_gridC + (size_t)rc0 * NCOIL);
    #pragma unroll
    for (int k = 0; k < 3; k++) {
        int idx = t + k * 256;
        int rc = idx / 6;
        int j  = idx - rc * 6;
        float2 a = T[rc][2 * j];
        float2 b = T[rc][2 * j + 1];
        dst[idx] = make_float4(a.x, a.y, b.x, b.y);
    }
}

// ---------------------------------------------------------------------------
// Interpolation: ONE WARP PER SAMPLE on coil-interleaved float2 grid.
// ---------------------------------------------------------------------------
#define WPB 8   // warps (samples) per block
__global__ void __launch_bounds__(32 * WPB) interp_kernel(const float* __restrict__ ktraj,
                                                          float* __restrict__ out) {
    __shared__ float2 s_part[WPB][72];
    __shared__ float2 s_out[NCOIL][WPB];
    const int warp = threadIdx.x >> 5;
    const int lane = threadIdx.x & 31;
    const int m = blockIdx.x * WPB + warp;

    float w = 0.0f;
    int   ki = 0;
    if (lane < 12) {
        int dim = lane >= 6 ? 1 : 0;
        int j   = lane - dim * 6;
        float om = ktraj[dim * MPTS + m];
        float tt = fmodf((om * 640.0f) / 6.2831855f, 640.0f);
        if (tt < 0.0f) tt += 640.0f;
        float base = floorf(tt);
        float k = base + (float)(j - 2);
        w = kbf(tt - k);
        ki = (int)k;
        if (ki < 0) ki += 640;
        else if (ki >= 640) ki -= 640;
    }

    const int e0 = lane, e1 = lane + 32, e2 = lane + 64;
    const int j0 = e0 / 12, j1 = e1 / 12;
    const int cc0 = e0 - j0 * 12, cc1 = e1 - j1 * 12, cc2 = e2 - 60;

    const unsigned FULL = 0xFFFFFFFFu;
    float wy0 = __shfl_sync(FULL, w, 6 + j0);
    float wy1 = __shfl_sync(FULL, w, 6 + j1);
    float wy2 = __shfl_sync(FULL, w, 11);
    int   iy0 = __shfl_sync(FULL, ki, 6 + j0);
    int   iy1 = __shfl_sync(FULL, ki, 6 + j1);
    int   iy2 = __shfl_sync(FULL, ki, 11);
    const int off0 = iy0 * NCOIL + cc0;
    const int off1 = iy1 * NCOIL + cc1;
    const int off2 = iy2 * NCOIL + cc2;
    const bool has2 = (lane < 8);

    float2 acc0 = make_float2(0.f, 0.f);
    float2 acc1 = make_float2(0.f, 0.f);
    float2 acc2 = make_float2(0.f, 0.f);

    #pragma unroll
    for (int i = 0; i < 6; i++) {
        float wx = __shfl_sync(FULL, w, i);
        int   ix = __shfl_sync(FULL, ki, i);
        const float2* __restrict__ rowp = g_gridC + (size_t)ix * (GQ * NCOIL);
        float2 v0 = __ldg(rowp + off0);
        float2 v1 = __ldg(rowp + off1);
        acc0.x += wx * v0.x; acc0.y += wx * v0.y;
        acc1.x += wx * v1.x; acc1.y += wx * v1.y;
        if (has2) {
            float2 v2 = __ldg(rowp + off2);
            acc2.x += wx * v2.x; acc2.y += wx * v2.y;
        }
    }

    s_part[warp][e0] = make_float2(wy0 * acc0.x, wy0 * acc0.y);
    s_part[warp][e1] = make_float2(wy1 * acc1.x, wy1 * acc1.y);
    if (has2) s_part[warp][e2] = make_float2(wy2 * acc2.x, wy2 * acc2.y);
    __syncwarp();

    if (lane < 12) {
        float rx = 0.f, ry = 0.f;
        #pragma unroll
        for (int j = 0; j < 6; j++) {
            float2 p = s_part[warp][j * 12 + lane];
            rx += p.x; ry += p.y;
        }
        s_out[lane][warp] = make_float2(rx, ry);
    }
    __syncthreads();

    if (threadIdx.x < NCOIL * WPB) {
        int c = threadIdx.x >> 3;
        int s = threadIdx.x & 7;
        ((float2*)out)[(size_t)c * MPTS + blockIdx.x * WPB + s] = s_out[c][s];
    }
}

// ---------------------------------------------------------------------------
extern "C" void kernel_launch(void* const* d_in, const int* in_sizes, int n_in,
                              void* d_out, int out_size) {
    const float* img_r = (const float*)d_in[0];
    const float* img_i = (const float*)d_in[1];
    const float* sm_r  = (const float*)d_in[2];
    const float* sm_i  = (const float*)d_in[3];
    const float* kt    = (const float*)d_in[4];
    float* out = (float*)d_out;

    apod_kernel<<<1, 640>>>();
    row_fft_kernel<<<dim3(160, NCOIL), 320>>>(img_r, img_i, sm_r, sm_i);
    col_fft_kernel<<<dim3(GQ / COLS_PER_BLK, NCOIL), 320>>>();
    transpose_kernel<<<(GQ * GQ) / TRC2, 256>>>();
    interp_kernel<<<MPTS / WPB, 32 * WPB>>>(kt, out);
}